// round 6
// baseline (speedup 1.0000x reference)
#include <cuda_runtime.h>
#include <math.h>

#define SIZE   1024
#define INPUT  1024
#define CTX    512
#define CMS    6
#define NSLOT  64
#define BATCH  128

// Scratch (device global — no allocation allowed)
__device__ float g_logT[BATCH * INPUT];   // logits transposed: [b][i]

__device__ __forceinline__ void fma2(unsigned long long& d,
                                     unsigned long long a,
                                     unsigned long long b) {
    asm("fma.rn.f32x2 %0, %1, %2, %3;" : "=l"(d) : "l"(a), "l"(b), "l"(d));
}
__device__ __forceinline__ unsigned long long dup2(float x) {
    unsigned long long r;
    asm("mov.b64 %0, {%1, %1};" : "=l"(r) : "f"(x));
    return r;
}

// ---------------------------------------------------------------------------
// Kernel 1: transpose logits (INPUT, BATCH) -> (BATCH, INPUT)
// ---------------------------------------------------------------------------
__global__ void transpose_logits_k(const float* __restrict__ in) {
    __shared__ float tile[32][33];
    int i0 = blockIdx.x * 32;
    int b0 = blockIdx.y * 32;
    int x = threadIdx.x, y = threadIdx.y;
    #pragma unroll
    for (int j = 0; j < 32; j += 8)
        tile[y + j][x] = in[(size_t)(i0 + y + j) * BATCH + (b0 + x)];
    __syncthreads();
    #pragma unroll
    for (int j = 0; j < 32; j += 8)
        g_logT[(size_t)(b0 + y + j) * INPUT + (i0 + x)] = tile[x][y + j];
}

// ---------------------------------------------------------------------------
// Kernel 2: FUSED. One block per neuron, 512 threads.
// Phase A: ctx hash for this neuron (warp w = K-chunk of 32, lane = b-quad),
//          ctxin from L2, proj via smem; 16 partials reduced in smem -> s_ctx.
// Phase B: warp-per-row gather-dot / out / update / copy over 4 slots/warp.
// ---------------------------------------------------------------------------
__global__ __launch_bounds__(512, 2) void fused_k(
        const float* __restrict__ proj,
        const float* __restrict__ pbias,
        const float* __restrict__ ctxin,
        const float* __restrict__ weights,
        const float* __restrict__ targets,
        const float* __restrict__ biasp,
        float* __restrict__ out,
        float* __restrict__ neww) {
    __shared__ float  s_proj[CTX * CMS];        // 12KB, layout [c*6 + m]
    __shared__ float2 s_part[16][32][12];       // 48KB partial sums
    __shared__ float  s_pb[CMS];
    __shared__ int    s_ctx[BATCH];

    const int s    = blockIdx.x;
    const int tid  = threadIdx.x;
    const int wid  = tid >> 5;
    const int lane = tid & 31;

    // ---- stage proj row of this neuron: gmem [m][c] -> smem [c][m] ----
    #pragma unroll
    for (int l = tid; l < CMS * CTX; l += 512) {
        const int m = l >> 9, c = l & 511;           // coalesced over c
        s_proj[c * CMS + m] = proj[((size_t)s * CMS + m) * CTX + c];
    }
    if (tid < CMS) s_pb[tid] = pbias[(size_t)s * CMS + tid];
    __syncthreads();

    // ---- Phase A: partial GEMM, warp wid covers c in [wid*32, wid*32+32) ----
    {
        unsigned long long acc[3][4];
        #pragma unroll
        for (int jp = 0; jp < 3; jp++)
            #pragma unroll
            for (int j = 0; j < 4; j++) acc[jp][j] = 0ull;

        const int c0 = wid * 32;
        #pragma unroll 4
        for (int cc = 0; cc < 32; cc++) {
            const int c = c0 + cc;
            const float4 xv =
                __ldg((const float4*)&ctxin[(size_t)c * BATCH + lane * 4]);
            const unsigned long long xb[4] = {
                dup2(xv.x), dup2(xv.y), dup2(xv.z), dup2(xv.w) };
            #pragma unroll
            for (int jp = 0; jp < 3; jp++) {
                const unsigned long long p2 =
                    *(const unsigned long long*)&s_proj[c * CMS + 2 * jp];
                fma2(acc[jp][0], p2, xb[0]);
                fma2(acc[jp][1], p2, xb[1]);
                fma2(acc[jp][2], p2, xb[2]);
                fma2(acc[jp][3], p2, xb[3]);
            }
        }
        #pragma unroll
        for (int jp = 0; jp < 3; jp++)
            #pragma unroll
            for (int j = 0; j < 4; j++) {
                union { unsigned long long u; float2 f; } cv;
                cv.u = acc[jp][j];
                s_part[wid][lane][jp * 4 + j] = cv.f;
            }
    }
    __syncthreads();

    // ---- K-reduction + threshold: thread b < 128 ----
    if (tid < BATCH) {
        const int bq = tid >> 2, j = tid & 3;
        int idx = 0;
        #pragma unroll
        for (int jp = 0; jp < 3; jp++) {
            float sx = 0.0f, sy = 0.0f;
            #pragma unroll
            for (int w = 0; w < 16; w++) {
                const float2 p = s_part[w][bq][jp * 4 + j];
                sx += p.x; sy += p.y;
            }
            if (sx > s_pb[2 * jp])     idx |= (1 << (2 * jp));
            if (sy > s_pb[2 * jp + 1]) idx |= (1 << (2 * jp + 1));
        }
        s_ctx[tid] = idx;
    }
    __syncthreads();

    // ---- Phase B: warp-per-row over 4 slots (interleaved for coalescing) ----
    int v[4];
    #pragma unroll
    for (int j = 0; j < 4; j++) v[j] = s_ctx[j * 32 + lane];

    const size_t nbase = (size_t)s * NSLOT * INPUT;
    const float bias = *biasp;

    #pragma unroll 1
    for (int it = 0; it < 4; it++) {
        const int slot = it * 16 + wid;
        const size_t rowoff = nbase + (size_t)slot * INPUT;
        const float4* wrow = (const float4*)(weights + rowoff);
        float4 w[8];
        #pragma unroll
        for (int k = 0; k < 8; k++) w[k] = __ldcs(wrow + k * 32 + lane);

        int   last    = -1;
        float lasttot = 0.0f;

        #pragma unroll
        for (int j = 0; j < 4; j++) {
            unsigned m = __ballot_sync(0xffffffffu, v[j] == slot);
            while (m) {
                const int bit = __ffs(m) - 1;
                m &= m - 1;
                const int bb = j * 32 + bit;
                const float4* xr = (const float4*)(g_logT + (size_t)bb * INPUT);
                float acc = 0.0f;
                #pragma unroll
                for (int k = 0; k < 8; k++) {
                    float4 x = __ldg(xr + k * 32 + lane);
                    acc += w[k].x * x.x + w[k].y * x.y
                         + w[k].z * x.z + w[k].w * x.w;
                }
                #pragma unroll
                for (int o = 16; o > 0; o >>= 1)
                    acc += __shfl_xor_sync(0xffffffffu, acc, o);
                if (lane == 0)
                    out[(size_t)s * BATCH + bb] = (s == 0) ? bias : acc;
                last = bb;          // ascending scan -> last-b-wins
                lasttot = acc;
            }
        }

        if (last >= 0) {
            float o  = (s == 0) ? bias : lasttot;
            float sg = 1.0f / (1.0f + expf(-o));
            sg = fminf(fmaxf(sg, 0.01f), 0.99f);
            const float g = 0.01f * (sg - __ldg(&targets[last]));
            const float4* xr = (const float4*)(g_logT + (size_t)last * INPUT);
            #pragma unroll
            for (int k = 0; k < 8; k++) {
                float4 x = __ldg(xr + k * 32 + lane);
                w[k].x = fminf(fmaxf(w[k].x - g * x.x, -5.0f), 5.0f);
                w[k].y = fminf(fmaxf(w[k].y - g * x.y, -5.0f), 5.0f);
                w[k].z = fminf(fmaxf(w[k].z - g * x.z, -5.0f), 5.0f);
                w[k].w = fminf(fmaxf(w[k].w - g * x.w, -5.0f), 5.0f);
            }
        }

        float4* orow = (float4*)(neww + rowoff);
        #pragma unroll
        for (int k = 0; k < 8; k++) __stcs(orow + k * 32 + lane, w[k]);
    }
}

// ---------------------------------------------------------------------------
extern "C" void kernel_launch(void* const* d_in, const int* in_sizes, int n_in,
                              void* d_out, int out_size) {
    const float* logits  = (const float*)d_in[0];  // (1024, 128)
    const float* ctxin   = (const float*)d_in[1];  // (512, 128)
    const float* targets = (const float*)d_in[2];  // (128,)
    const float* proj    = (const float*)d_in[3];  // (1024, 6, 512)
    const float* pbias   = (const float*)d_in[4];  // (1024, 6, 1)
    const float* weights = (const float*)d_in[5];  // (1024, 64, 1024)
    const float* biasp   = (const float*)d_in[6];  // ()

    float* out  = (float*)d_out;                   // (1024, 128)
    float* neww = out + (size_t)SIZE * BATCH;      // (1024, 64, 1024)

    dim3 tb(32, 8), tg(INPUT / 32, BATCH / 32);
    transpose_logits_k<<<tg, tb>>>(logits);
    fused_k<<<SIZE, 512>>>(proj, pbias, ctxin, weights, targets, biasp,
                           out, neww);
}

// round 7
// speedup vs baseline: 1.0867x; 1.0867x over previous
#include <cuda_runtime.h>
#include <math.h>

#define SIZE   1024
#define INPUT  1024
#define CTX    512
#define CMS    6
#define NSLOT  64
#define BATCH  128
#define SPER   8      // neurons per group in ctx kernels
#define KSPLIT 4
#define KPART  (CTX / KSPLIT)   // 128
#define KBLK   32

// Scratch (device globals — no allocation allowed)
__device__ float g_logT[BATCH * INPUT];            // logits^T: [b][i]
__device__ int   g_ctx [SIZE * BATCH];             // context index: [s][b]
__device__ float g_part[KSPLIT * SIZE * CMS * BATCH];  // 12.6MB partials

__device__ __forceinline__ void fma2(unsigned long long& d,
                                     unsigned long long a,
                                     unsigned long long b) {
    asm("fma.rn.f32x2 %0, %1, %2, %3;" : "=l"(d) : "l"(a), "l"(b), "l"(d));
}
__device__ __forceinline__ unsigned long long dup2(float x) {
    unsigned long long r;
    asm("mov.b64 %0, {%1, %1};" : "=l"(r) : "f"(x));
    return r;
}

// ---------------------------------------------------------------------------
// Kernel 1: ctx-hash partial GEMM. grid = 128 groups x 4 k-parts.
// Block (g, kp): 8 warps, warp sl = neuron g*8+sl over c in [kp*128, kp*128+128).
// Lane = b-quad; 3 m-pair f32x2 accumulators x 4 b (24 regs).
// Writes partial sums to g_part[kp][s][m][b] (coalesced float4 per m).
// ---------------------------------------------------------------------------
__global__ __launch_bounds__(256) void ctx_part_k(
        const float* __restrict__ proj,
        const float* __restrict__ ctxin) {
    __shared__ float s_x[KBLK][BATCH];        // 16KB, shared by 8 neurons
    __shared__ float s_p[SPER][KBLK][CMS];    // 6KB  [sl][c][m]
    const int gid  = blockIdx.x;
    const int g    = gid >> 2;
    const int kp   = gid & 3;
    const int tid  = threadIdx.x;
    const int sl   = tid >> 5;
    const int lane = tid & 31;
    const int s0   = g * SPER;

    unsigned long long acc[3][4];
    #pragma unroll
    for (int jp = 0; jp < 3; jp++)
        #pragma unroll
        for (int j = 0; j < 4; j++) acc[jp][j] = 0ull;

    for (int kb = 0; kb < KPART; kb += KBLK) {
        const int cbase = kp * KPART + kb;
        #pragma unroll
        for (int l = tid; l < KBLK * BATCH; l += 256)
            s_x[l >> 7][l & 127] =
                ctxin[(size_t)(cbase + (l >> 7)) * BATCH + (l & 127)];
        #pragma unroll
        for (int l = tid; l < SPER * CMS * KBLK; l += 256) {
            const int row = l >> 5;           // sl*CMS + m
            const int c   = l & 31;
            s_p[row / CMS][c][row % CMS] =
                proj[((size_t)(s0 + row / CMS) * CMS + (row % CMS)) * CTX
                     + cbase + c];
        }
        __syncthreads();

        #pragma unroll 8
        for (int c = 0; c < KBLK; c++) {
            const float4 xv = *(const float4*)&s_x[c][lane * 4];
            const unsigned long long xb[4] = {
                dup2(xv.x), dup2(xv.y), dup2(xv.z), dup2(xv.w) };
            #pragma unroll
            for (int jp = 0; jp < 3; jp++) {
                const unsigned long long p2 =
                    *(const unsigned long long*)&s_p[sl][c][2 * jp];
                fma2(acc[jp][0], p2, xb[0]);
                fma2(acc[jp][1], p2, xb[1]);
                fma2(acc[jp][2], p2, xb[2]);
                fma2(acc[jp][3], p2, xb[3]);
            }
        }
        __syncthreads();
    }

    // write partials: per m-pair assemble float4 over this thread's b-quad
    const size_t base = ((size_t)kp * SIZE + (s0 + sl)) * CMS * BATCH;
    #pragma unroll
    for (int jp = 0; jp < 3; jp++) {
        float4 lo, hi;   // m = 2jp, 2jp+1
        union { unsigned long long u; float2 f; } c0, c1, c2, c3;
        c0.u = acc[jp][0]; c1.u = acc[jp][1];
        c2.u = acc[jp][2]; c3.u = acc[jp][3];
        lo = make_float4(c0.f.x, c1.f.x, c2.f.x, c3.f.x);
        hi = make_float4(c0.f.y, c1.f.y, c2.f.y, c3.f.y);
        *(float4*)&g_part[base + (size_t)(2 * jp) * BATCH + lane * 4]     = lo;
        *(float4*)&g_part[base + (size_t)(2 * jp + 1) * BATCH + lane * 4] = hi;
    }
}

// ---------------------------------------------------------------------------
// Kernel 2: reduce partials -> threshold -> g_ctx; folds logits transpose.
// grid 256, 512 threads: thread = (sl in [0,4), b); s = bx*4 + sl.
// ---------------------------------------------------------------------------
__global__ __launch_bounds__(512) void idx_k(
        const float* __restrict__ pbias,
        const float* __restrict__ logits) {
    __shared__ float s_t[4][BATCH];
    const int tid = threadIdx.x;
    const int sl  = tid >> 7;
    const int b   = tid & 127;
    const int s   = blockIdx.x * 4 + sl;
    const int i0  = blockIdx.x * 4;

    // stage 4 logits rows (coalesced)
    s_t[sl][b] = logits[(size_t)(i0 + sl) * BATCH + b];

    // reduce K-partials and threshold
    int idx = 0;
    const size_t sbase = (size_t)s * CMS * BATCH + b;
    #pragma unroll
    for (int m = 0; m < CMS; m++) {
        float sum = 0.0f;
        #pragma unroll
        for (int kpp = 0; kpp < KSPLIT; kpp++)
            sum += g_part[(size_t)kpp * SIZE * CMS * BATCH
                          + sbase + (size_t)m * BATCH];
        if (sum > __ldg(&pbias[(size_t)s * CMS + m])) idx |= (1 << m);
    }
    g_ctx[(size_t)s * BATCH + b] = idx;

    __syncthreads();
    // transposed store: column i0+sl of g_logT
    g_logT[(size_t)b * INPUT + i0 + sl] = s_t[sl][b];
}

// ---------------------------------------------------------------------------
// Kernel 3: warp-per-row fused gather-dot / out / update / scatter-copy.
// (unchanged from best round: 85.2us, 72% DRAM)
// ---------------------------------------------------------------------------
__global__ __launch_bounds__(256, 4) void main_k(
        const float* __restrict__ weights,
        const float* __restrict__ targets,
        const float* __restrict__ biasp,
        float* __restrict__ out,
        float* __restrict__ neww) {
    const int s    = blockIdx.y;
    const int tid  = threadIdx.x;
    const int lane = tid & 31;
    const int wid  = tid >> 5;
    const int slot = blockIdx.x * 8 + wid;

    __shared__ int s_ctx[BATCH];
    if (tid < BATCH) s_ctx[tid] = g_ctx[(size_t)s * BATCH + tid];

    const size_t rowoff = ((size_t)s * NSLOT + slot) * INPUT;
    const float4* wrow = (const float4*)(weights + rowoff);
    float4 w[8];
    #pragma unroll
    for (int k = 0; k < 8; k++) w[k] = __ldcs(wrow + k * 32 + lane);

    __syncthreads();

    int   last    = -1;
    float lasttot = 0.0f;

    #pragma unroll
    for (int j = 0; j < 4; j++) {
        const int bb0 = j * 32;
        const int v = s_ctx[bb0 + lane];
        unsigned m = __ballot_sync(0xffffffffu, v == slot);
        while (m) {
            const int bit = __ffs(m) - 1;
            m &= m - 1;
            const int bb = bb0 + bit;
            const float4* xr = (const float4*)(g_logT + (size_t)bb * INPUT);
            float acc = 0.0f;
            #pragma unroll
            for (int k = 0; k < 8; k++) {
                float4 x = __ldg(xr + k * 32 + lane);
                acc += w[k].x * x.x + w[k].y * x.y + w[k].z * x.z + w[k].w * x.w;
            }
            #pragma unroll
            for (int o = 16; o > 0; o >>= 1)
                acc += __shfl_xor_sync(0xffffffffu, acc, o);
            if (lane == 0)
                out[(size_t)s * BATCH + bb] = (s == 0) ? *biasp : acc;
            last = bb;            // ascending scan -> last-b-wins
            lasttot = acc;
        }
    }

    if (last >= 0) {
        float o  = (s == 0) ? *biasp : lasttot;
        float sg = 1.0f / (1.0f + expf(-o));
        sg = fminf(fmaxf(sg, 0.01f), 0.99f);
        const float g = 0.01f * (sg - __ldg(&targets[last]));
        const float4* xr = (const float4*)(g_logT + (size_t)last * INPUT);
        #pragma unroll
        for (int k = 0; k < 8; k++) {
            float4 x = __ldg(xr + k * 32 + lane);
            w[k].x = fminf(fmaxf(w[k].x - g * x.x, -5.0f), 5.0f);
            w[k].y = fminf(fmaxf(w[k].y - g * x.y, -5.0f), 5.0f);
            w[k].z = fminf(fmaxf(w[k].z - g * x.z, -5.0f), 5.0f);
            w[k].w = fminf(fmaxf(w[k].w - g * x.w, -5.0f), 5.0f);
        }
    }

    float4* orow = (float4*)(neww + rowoff);
    #pragma unroll
    for (int k = 0; k < 8; k++) __stcs(orow + k * 32 + lane, w[k]);
}

// ---------------------------------------------------------------------------
extern "C" void kernel_launch(void* const* d_in, const int* in_sizes, int n_in,
                              void* d_out, int out_size) {
    const float* logits  = (const float*)d_in[0];  // (1024, 128)
    const float* ctxin   = (const float*)d_in[1];  // (512, 128)
    const float* targets = (const float*)d_in[2];  // (128,)
    const float* proj    = (const float*)d_in[3];  // (1024, 6, 512)
    const float* pbias   = (const float*)d_in[4];  // (1024, 6, 1)
    const float* weights = (const float*)d_in[5];  // (1024, 64, 1024)
    const float* biasp   = (const float*)d_in[6];  // ()

    float* out  = (float*)d_out;                   // (1024, 128)
    float* neww = out + (size_t)SIZE * BATCH;      // (1024, 64, 1024)

    ctx_part_k<<<(SIZE / SPER) * KSPLIT, 256>>>(proj, ctxin);
    idx_k<<<SIZE / 4, 512>>>(pbias, logits);
    main_k<<<dim3(NSLOT / 8, SIZE), 256>>>(weights, targets, biasp, out, neww);
}